// round 2
// baseline (speedup 1.0000x reference)
#include <cuda_runtime.h>
#include <cuda_bf16.h>
#include <float.h>

// Problem constants (fixed by the dataset)
#define MAXN 20000
#define MAXE 320000
#define MAXEP (MAXE + MAXN)
#define D  64
#define H  10
#define HD 640
#define H1DIM 1500

// ----------------------------- scratch (static, allocation-free) ------------
__device__ __align__(16) float g_xl  [(size_t)MAXN * HD];   // GAT-transformed features
__device__ __align__(16) float g_asrc[(size_t)MAXN * H];
__device__ __align__(16) float g_adst[(size_t)MAXN * H];
__device__ __align__(16) float g_m   [(size_t)MAXN * H];    // segment max
__device__ __align__(16) float g_den [(size_t)MAXN * H];    // segment sum of exp
__device__ __align__(16) float g_ex  [(size_t)MAXEP * H];   // per-edge exp(alpha - m)
__device__ __align__(16) float g_x1  [(size_t)MAXN * HD];   // GAT output
__device__ __align__(16) float g_xw  [(size_t)MAXN * HD];   // x1 @ W_gcn
__device__ __align__(16) float g_x2  [(size_t)MAXN * HD];   // GCN output
__device__ __align__(16) float g_deg [MAXN];
__device__ __align__(16) float g_pmax[HD];
__device__ __align__(16) float g_psum[HD];
__device__ __align__(16) float g_h1  [H1DIM];

// ----------------------------- helpers --------------------------------------
__device__ __forceinline__ float atomicMaxFloat(float* addr, float value) {
    if (value >= 0.0f)
        return __int_as_float(atomicMax((int*)addr, __float_as_int(value)));
    else
        return __uint_as_float(atomicMin((unsigned int*)addr, __float_as_uint(value)));
}

// ----------------------------- init kernels ---------------------------------
__global__ void k_fill(float* __restrict__ p, float v, int n) {
    int i = blockIdx.x * blockDim.x + threadIdx.x;
    if (i < n) p[i] = v;
}

__global__ void k_bias_init(float* __restrict__ dst, const float* __restrict__ bias, int n) {
    int i = blockIdx.x * blockDim.x + threadIdx.x;  // over N*HD
    if (i < n) dst[i] = bias[i % HD];
}

__global__ void k_relu(float* __restrict__ p, int n) {
    int i = blockIdx.x * blockDim.x + threadIdx.x;
    if (i < n) p[i] = fmaxf(p[i], 0.0f);
}

// ----------------------------- SGEMM: C[M,Nn] = A[M,K] @ B[K,Nn] -------------
#define BM 128
#define BN 128
#define BK 8
#define TM 8
#define TN 8
__global__ __launch_bounds__(256)
void k_sgemm(const float* __restrict__ A, const float* __restrict__ B,
             float* __restrict__ C, int M, int Nn, int K) {
    __shared__ float As[BK][BM];
    __shared__ float Bs[BK][BN];
    const int tid = threadIdx.x;
    const int nTilesX = Nn / BN;
    const int bx = blockIdx.x % nTilesX;
    const int by = blockIdx.x / nTilesX;
    const int rowBase = by * BM;
    const int colBase = bx * BN;
    const int tr = tid / 16;
    const int tc = tid % 16;

    const int aRow = tid >> 1;            // 0..127
    const int aCol = (tid & 1) * 4;       // 0 or 4
    const int bRow = tid >> 5;            // 0..7
    const int bCol = (tid & 31) * 4;      // 0..124

    float acc[TM][TN];
#pragma unroll
    for (int i = 0; i < TM; i++)
#pragma unroll
        for (int j = 0; j < TN; j++) acc[i][j] = 0.0f;

    for (int k0 = 0; k0 < K; k0 += BK) {
        // load A tile (transposed into shared)
        float4 av;
        const int gr = rowBase + aRow;
        if (gr < M) av = *(const float4*)&A[(size_t)gr * K + k0 + aCol];
        else        av = make_float4(0.f, 0.f, 0.f, 0.f);
        As[aCol + 0][aRow] = av.x;
        As[aCol + 1][aRow] = av.y;
        As[aCol + 2][aRow] = av.z;
        As[aCol + 3][aRow] = av.w;
        // load B tile
        float4 bv = *(const float4*)&B[(size_t)(k0 + bRow) * Nn + colBase + bCol];
        *(float4*)&Bs[bRow][bCol] = bv;
        __syncthreads();

#pragma unroll
        for (int k = 0; k < BK; k++) {
            float ar[TM], br[TN];
#pragma unroll
            for (int i = 0; i < TM; i++) ar[i] = As[k][tr * TM + i];
#pragma unroll
            for (int j = 0; j < TN; j++) br[j] = Bs[k][tc * TN + j];
#pragma unroll
            for (int i = 0; i < TM; i++)
#pragma unroll
                for (int j = 0; j < TN; j++) acc[i][j] += ar[i] * br[j];
        }
        __syncthreads();
    }

#pragma unroll
    for (int i = 0; i < TM; i++) {
        const int gr = rowBase + tr * TM + i;
        if (gr >= M) break;
#pragma unroll
        for (int j = 0; j < TN; j += 4) {
            *(float4*)&C[(size_t)gr * Nn + colBase + tc * TN + j] =
                make_float4(acc[i][j], acc[i][j + 1], acc[i][j + 2], acc[i][j + 3]);
        }
    }
}

// ----------------------------- attention scores ------------------------------
// one warp per (node, head): a_src[n,h] = dot(xl[n,h,:], att_src[h,:]); same for dst
__global__ void k_att(const float* __restrict__ xl,
                      const float* __restrict__ att_src, const float* __restrict__ att_dst,
                      float* __restrict__ asrc, float* __restrict__ adst, int N) {
    int warp = (blockIdx.x * blockDim.x + threadIdx.x) >> 5;
    int lane = threadIdx.x & 31;
    if (warp >= N * H) return;
    int n = warp / H, h = warp - n * H;
    const float* p = xl + (size_t)n * HD + h * D;
    float x0 = p[lane], x1v = p[lane + 32];
    float s1 = x0 * att_src[h * D + lane] + x1v * att_src[h * D + lane + 32];
    float s2 = x0 * att_dst[h * D + lane] + x1v * att_dst[h * D + lane + 32];
#pragma unroll
    for (int o = 16; o > 0; o >>= 1) {
        s1 += __shfl_down_sync(0xffffffffu, s1, o);
        s2 += __shfl_down_sync(0xffffffffu, s2, o);
    }
    if (lane == 0) { asrc[warp] = s1; adst[warp] = s2; }
}

// ----------------------------- alpha + segment max + deg --------------------
__global__ void k_alpha_max(const int* __restrict__ ei,
                            const float* __restrict__ asrc, const float* __restrict__ adst,
                            float* __restrict__ m, float* __restrict__ deg, int E, int N) {
    int idx = blockIdx.x * blockDim.x + threadIdx.x;
    int EP = E + N;
    if (idx >= EP * H) return;
    int e = idx / H, h = idx - e * H;
    int src, dst;
    if (e < E) { src = ei[e]; dst = ei[E + e]; }
    else       { src = dst = e - E; }
    float a = asrc[src * H + h] + adst[dst * H + h];
    a = a > 0.0f ? a : 0.2f * a;            // leaky relu
    atomicMaxFloat(&m[dst * H + h], a);
    if (h == 0) atomicAdd(&deg[dst], 1.0f);
}

// ----------------------------- exp + segment sum ----------------------------
__global__ void k_exp_sum(const int* __restrict__ ei,
                          const float* __restrict__ asrc, const float* __restrict__ adst,
                          const float* __restrict__ m,
                          float* __restrict__ ex, float* __restrict__ den, int E, int N) {
    int idx = blockIdx.x * blockDim.x + threadIdx.x;
    int EP = E + N;
    if (idx >= EP * H) return;
    int e = idx / H, h = idx - e * H;
    int src, dst;
    if (e < E) { src = ei[e]; dst = ei[E + e]; }
    else       { src = dst = e - E; }
    float a = asrc[src * H + h] + adst[dst * H + h];
    a = a > 0.0f ? a : 0.2f * a;
    float v = expf(a - m[dst * H + h]);
    ex[idx] = v;
    atomicAdd(&den[dst * H + h], v);
}

// ----------------------------- GAT message aggregation ----------------------
// one warp per edge: x1[dst,:] += xl[src,:] * w[h]
__global__ void k_gat_agg(const int* __restrict__ ei,
                          const float* __restrict__ xl,
                          const float* __restrict__ ex, const float* __restrict__ den,
                          float* __restrict__ x1, int E, int N) {
    int warp = (blockIdx.x * blockDim.x + threadIdx.x) >> 5;
    int lane = threadIdx.x & 31;
    int EP = E + N;
    if (warp >= EP) return;
    int e = warp;
    int src, dst;
    if (e < E) { src = ei[e]; dst = ei[E + e]; }
    else       { src = dst = e - E; }
    float wv = 0.0f;
    if (lane < H) wv = ex[(size_t)e * H + lane] / (den[dst * H + lane] + 1e-16f);
    const float* xs = xl + (size_t)src * HD;
    float*       xd = x1 + (size_t)dst * HD;
#pragma unroll
    for (int j = 0; j < HD / 32; j++) {
        int i = j * 32 + lane;
        int h = i >> 6;
        float w = __shfl_sync(0xffffffffu, wv, h);
        atomicAdd(&xd[i], xs[i] * w);
    }
}

// ----------------------------- GCN aggregation ------------------------------
__global__ void k_gcn_agg(const int* __restrict__ ei,
                          const float* __restrict__ xw, const float* __restrict__ deg,
                          float* __restrict__ x2, int E, int N) {
    int warp = (blockIdx.x * blockDim.x + threadIdx.x) >> 5;
    int lane = threadIdx.x & 31;
    int EP = E + N;
    if (warp >= EP) return;
    int e = warp;
    int src, dst;
    if (e < E) { src = ei[e]; dst = ei[E + e]; }
    else       { src = dst = e - E; }
    float nrm = rsqrtf(deg[src]) * rsqrtf(deg[dst]);
    const float* xs = xw + (size_t)src * HD;
    float*       xd = x2 + (size_t)dst * HD;
#pragma unroll
    for (int j = 0; j < HD / 32; j++) {
        int i = j * 32 + lane;
        atomicAdd(&xd[i], xs[i] * nrm);
    }
}

// ----------------------------- pooling (relu fused on read) -----------------
__global__ void k_pool(const float* __restrict__ x2, float* __restrict__ pmax,
                       float* __restrict__ psum, int N) {
    int c = threadIdx.x;                         // 640 threads = columns
    float mx = 0.0f, sm = 0.0f;
    for (int n = blockIdx.x; n < N; n += gridDim.x) {
        float v = x2[(size_t)n * HD + c];
        v = fmaxf(v, 0.0f);                      // relu
        mx = fmaxf(mx, v);
        sm += v;
    }
    atomicMax((int*)&pmax[c], __float_as_int(mx));   // values >= 0, init 0
    atomicAdd(&psum[c], sm);
}

// ----------------------------- MLP ------------------------------------------
__global__ void k_mlp1(const float* __restrict__ pmax, const float* __restrict__ psum,
                       const float* __restrict__ W1, const float* __restrict__ b1,
                       float* __restrict__ h1, int N) {
    int j = blockIdx.x * blockDim.x + threadIdx.x;
    if (j >= H1DIM) return;
    float acc = b1[j];
    float invN = 1.0f / (float)N;
    for (int k = 0; k < HD; k++)
        acc += pmax[k] * W1[(size_t)k * H1DIM + j];
    for (int k = 0; k < HD; k++)
        acc += psum[k] * invN * W1[(size_t)(HD + k) * H1DIM + j];
    h1[j] = fmaxf(acc, 0.0f);
}

__global__ void k_mlp2(const float* __restrict__ h1, const float* __restrict__ W2,
                       const float* __restrict__ b2, float* __restrict__ out) {
    __shared__ float acc[10];
    int tid = threadIdx.x;
    if (tid < 10) acc[tid] = 0.0f;
    __syncthreads();
    float part[10];
#pragma unroll
    for (int j = 0; j < 10; j++) part[j] = 0.0f;
    for (int k = tid; k < H1DIM; k += 256) {
        float hv = h1[k];
#pragma unroll
        for (int j = 0; j < 10; j++) part[j] += hv * W2[k * 10 + j];
    }
#pragma unroll
    for (int j = 0; j < 10; j++) atomicAdd(&acc[j], part[j]);
    __syncthreads();
    if (tid < 10) out[tid] = acc[tid] + b2[tid];
}

// ----------------------------- launch ---------------------------------------
static inline int cdiv(int a, int b) { return (a + b - 1) / b; }

extern "C" void kernel_launch(void* const* d_in, const int* in_sizes, int n_in,
                              void* d_out, int out_size) {
    const float* x       = (const float*)d_in[0];
    const float* W_gat   = (const float*)d_in[1];
    const float* att_src = (const float*)d_in[2];
    const float* att_dst = (const float*)d_in[3];
    const float* b_gat   = (const float*)d_in[4];
    const float* W_gcn   = (const float*)d_in[5];
    const float* b_gcn   = (const float*)d_in[6];
    const float* W1      = (const float*)d_in[7];
    const float* b1      = (const float*)d_in[8];
    const float* W2      = (const float*)d_in[9];
    const float* b2      = (const float*)d_in[10];
    const int*   ei      = (const int*)d_in[11];   // int32: JAX x64 is disabled

    const int N  = in_sizes[0] / D;
    const int E  = in_sizes[11] / 2;
    const int EP = E + N;
    float* out = (float*)d_out;

    // resolve scratch symbol addresses (pure lookups; capture-safe)
    float *p_xl, *p_asrc, *p_adst, *p_m, *p_den, *p_ex, *p_x1, *p_xw, *p_x2,
          *p_deg, *p_pmax, *p_psum, *p_h1;
    cudaGetSymbolAddress((void**)&p_xl,   g_xl);
    cudaGetSymbolAddress((void**)&p_asrc, g_asrc);
    cudaGetSymbolAddress((void**)&p_adst, g_adst);
    cudaGetSymbolAddress((void**)&p_m,    g_m);
    cudaGetSymbolAddress((void**)&p_den,  g_den);
    cudaGetSymbolAddress((void**)&p_ex,   g_ex);
    cudaGetSymbolAddress((void**)&p_x1,   g_x1);
    cudaGetSymbolAddress((void**)&p_xw,   g_xw);
    cudaGetSymbolAddress((void**)&p_x2,   g_x2);
    cudaGetSymbolAddress((void**)&p_deg,  g_deg);
    cudaGetSymbolAddress((void**)&p_pmax, g_pmax);
    cudaGetSymbolAddress((void**)&p_psum, g_psum);
    cudaGetSymbolAddress((void**)&p_h1,   g_h1);

    const int NHD = N * HD;
    const int NH  = N * H;

    // ---- init accumulators (must happen every replay) ----
    k_fill<<<cdiv(NH, 256), 256>>>(p_m, -FLT_MAX, NH);
    k_fill<<<cdiv(NH, 256), 256>>>(p_den, 0.0f, NH);
    k_fill<<<cdiv(N, 256), 256>>>(p_deg, 0.0f, N);
    k_fill<<<cdiv(HD, 256), 256>>>(p_pmax, 0.0f, HD);
    k_fill<<<cdiv(HD, 256), 256>>>(p_psum, 0.0f, HD);
    k_bias_init<<<cdiv(NHD, 256), 256>>>(p_x1, b_gat, NHD);
    k_bias_init<<<cdiv(NHD, 256), 256>>>(p_x2, b_gcn, NHD);

    // ---- GAT ----
    // xl = x @ W_gat   (M=N, K=64, Nn=640)
    k_sgemm<<<cdiv(N, BM) * (HD / BN), 256>>>(x, W_gat, p_xl, N, HD, D);
    k_att<<<cdiv(NH * 32, 256), 256>>>(p_xl, att_src, att_dst, p_asrc, p_adst, N);
    k_alpha_max<<<cdiv(EP * H, 256), 256>>>(ei, p_asrc, p_adst, p_m, p_deg, E, N);
    k_exp_sum<<<cdiv(EP * H, 256), 256>>>(ei, p_asrc, p_adst, p_m, p_ex, p_den, E, N);
    k_gat_agg<<<cdiv(EP * 32, 256), 256>>>(ei, p_xl, p_ex, p_den, p_x1, E, N);
    k_relu<<<cdiv(NHD, 256), 256>>>(p_x1, NHD);

    // ---- GCN ----
    // xw = x1 @ W_gcn  (M=N, K=640, Nn=640)
    k_sgemm<<<cdiv(N, BM) * (HD / BN), 256>>>(p_x1, W_gcn, p_xw, N, HD, HD);
    k_gcn_agg<<<cdiv(EP * 32, 256), 256>>>(ei, p_xw, p_deg, p_x2, E, N);

    // ---- pool + MLP head ----
    k_pool<<<256, HD>>>(p_x2, p_pmax, p_psum, N);
    k_mlp1<<<cdiv(H1DIM, 256), 256>>>(p_pmax, p_psum, W1, b1, p_h1, N);
    k_mlp2<<<1, 256>>>(p_h1, W2, b2, out);
}

// round 3
// speedup vs baseline: 1.2590x; 1.2590x over previous
#include <cuda_runtime.h>
#include <float.h>

// Problem constants (fixed by the dataset)
#define MAXN 20000
#define MAXE 320000
#define MAXEP (MAXE + MAXN)
#define D  64
#define H  10
#define HD 640
#define H1DIM 1500

// ----------------------------- scratch (static, allocation-free) ------------
__device__ __align__(16) float g_xl  [(size_t)MAXN * HD];
__device__ __align__(16) float g_x1  [(size_t)MAXN * HD];
__device__ __align__(16) float g_xw  [(size_t)MAXN * HD];
__device__ __align__(16) float g_x2  [(size_t)MAXN * HD];
__device__ __align__(16) float g_asrc[(size_t)MAXN * H];
__device__ __align__(16) float g_adst[(size_t)MAXN * H];
__device__ __align__(16) float g_pmax[HD];
__device__ __align__(16) float g_psum[HD];
__device__ __align__(16) float g_h1  [H1DIM];
__device__ int g_cnt   [MAXN];
__device__ int g_rowptr[MAXN + 1];
__device__ int g_cursor[MAXN];
__device__ int g_csrc  [MAXEP];

// ----------------------------- init -----------------------------------------
__global__ void k_init(int* __restrict__ cnt, float* __restrict__ pmax,
                       float* __restrict__ psum, int N) {
    int i = blockIdx.x * blockDim.x + threadIdx.x;
    if (i < N) cnt[i] = 0;
    else if (i < N + HD) pmax[i - N] = 0.0f;
    else if (i < N + 2 * HD) psum[i - N - HD] = 0.0f;
}

// ----------------------------- CSR build -------------------------------------
__global__ void k_count(const int* __restrict__ ei, int* __restrict__ cnt, int E, int N) {
    int e = blockIdx.x * blockDim.x + threadIdx.x;
    int EP = E + N;
    if (e >= EP) return;
    int dst = (e < E) ? ei[E + e] : (e - E);
    atomicAdd(&cnt[dst], 1);
}

__global__ __launch_bounds__(1024)
void k_scan(const int* __restrict__ cnt, int* __restrict__ rowptr,
            int* __restrict__ cursor, int N, int EP) {
    __shared__ int sums[1024];
    int t = threadIdx.x;
    int per = (N + 1023) / 1024;
    int start = t * per;
    int end = min(start + per, N);
    int s = 0;
    for (int i = start; i < end; i++) s += cnt[i];
    sums[t] = s;
    __syncthreads();
    int mine = s;
    // Hillis-Steele inclusive scan
    for (int off = 1; off < 1024; off <<= 1) {
        int o = (t >= off) ? sums[t - off] : 0;
        __syncthreads();
        sums[t] += o;
        __syncthreads();
    }
    int run = sums[t] - mine;  // exclusive prefix for this thread's chunk
    for (int i = start; i < end; i++) {
        rowptr[i] = run;
        cursor[i] = run;
        run += cnt[i];
    }
    if (t == 0) rowptr[N] = EP;
}

__global__ void k_scatter(const int* __restrict__ ei, int* __restrict__ cursor,
                          int* __restrict__ csrc, int E, int N) {
    int e = blockIdx.x * blockDim.x + threadIdx.x;
    int EP = E + N;
    if (e >= EP) return;
    int src, dst;
    if (e < E) { src = ei[e]; dst = ei[E + e]; }
    else       { src = dst = e - E; }
    int pos = atomicAdd(&cursor[dst], 1);
    csrc[pos] = src;
}

// ----------------------------- SGEMM: C[M,Nn] = A[M,K] @ B[K,Nn] --------------
// Optional fused attention-score epilogue (GEMM1 only): each 128-col tile
// covers exactly 2 heads (D=64); computes asrc/adst dot products in-epilogue.
#define BM 128
#define BN 128
#define BK 8
#define TM 8
#define TN 8
template <bool ATT>
__global__ __launch_bounds__(256)
void k_sgemm(const float* __restrict__ A, const float* __restrict__ B,
             float* __restrict__ C, int M, int Nn, int K,
             const float* __restrict__ att_src, const float* __restrict__ att_dst,
             float* __restrict__ asrc, float* __restrict__ adst) {
    __shared__ float As[BK][BM];
    __shared__ float Bs[BK][BN];
    const int tid = threadIdx.x;
    const int nTilesX = Nn / BN;
    const int bx = blockIdx.x % nTilesX;
    const int by = blockIdx.x / nTilesX;
    const int rowBase = by * BM;
    const int colBase = bx * BN;
    const int tr = tid / 16;
    const int tc = tid % 16;

    const int aRow = tid >> 1;
    const int aCol = (tid & 1) * 4;
    const int bRow = tid >> 5;
    const int bCol = (tid & 31) * 4;

    float acc[TM][TN];
#pragma unroll
    for (int i = 0; i < TM; i++)
#pragma unroll
        for (int j = 0; j < TN; j++) acc[i][j] = 0.0f;

    // initial global loads
    float4 av, bv;
    {
        const int gr = rowBase + aRow;
        if (gr < M) av = *(const float4*)&A[(size_t)gr * K + aCol];
        else        av = make_float4(0.f, 0.f, 0.f, 0.f);
        bv = *(const float4*)&B[(size_t)bRow * Nn + colBase + bCol];
    }

    for (int k0 = 0; k0 < K; k0 += BK) {
        // stage current tile
        As[aCol + 0][aRow] = av.x;
        As[aCol + 1][aRow] = av.y;
        As[aCol + 2][aRow] = av.z;
        As[aCol + 3][aRow] = av.w;
        *(float4*)&Bs[bRow][bCol] = bv;
        __syncthreads();

        // prefetch next tile
        if (k0 + BK < K) {
            const int gr = rowBase + aRow;
            if (gr < M) av = *(const float4*)&A[(size_t)gr * K + k0 + BK + aCol];
            else        av = make_float4(0.f, 0.f, 0.f, 0.f);
            bv = *(const float4*)&B[(size_t)(k0 + BK + bRow) * Nn + colBase + bCol];
        }

#pragma unroll
        for (int k = 0; k < BK; k++) {
            float ar[TM], br[TN];
#pragma unroll
            for (int i = 0; i < TM; i++) ar[i] = As[k][tr * TM + i];
#pragma unroll
            for (int j = 0; j < TN; j++) br[j] = Bs[k][tc * TN + j];
#pragma unroll
            for (int i = 0; i < TM; i++)
#pragma unroll
                for (int j = 0; j < TN; j++) acc[i][j] += ar[i] * br[j];
        }
        __syncthreads();
    }

    // write C
#pragma unroll
    for (int i = 0; i < TM; i++) {
        const int gr = rowBase + tr * TM + i;
        if (gr < M) {
#pragma unroll
            for (int j = 0; j < TN; j += 4) {
                *(float4*)&C[(size_t)gr * Nn + colBase + tc * TN + j] =
                    make_float4(acc[i][j], acc[i][j + 1], acc[i][j + 2], acc[i][j + 3]);
            }
        }
    }

    if (ATT) {
        // head covered by this thread's 8 columns
        const int hloc = tc >> 3;                 // 0 or 1
        const int h = bx * 2 + hloc;              // global head
        const int cih = (tc & 7) * 8;             // col-in-head base
        float as[8], ad[8];
#pragma unroll
        for (int j = 0; j < 8; j++) {
            as[j] = att_src[h * D + cih + j];
            ad[j] = att_dst[h * D + cih + j];
        }
#pragma unroll
        for (int i = 0; i < TM; i++) {
            float ps = 0.f, pd = 0.f;
#pragma unroll
            for (int j = 0; j < TN; j++) { ps += acc[i][j] * as[j]; pd += acc[i][j] * ad[j]; }
            // reduce across the 8 threads (consecutive tids) covering this head
            ps += __shfl_down_sync(0xffffffffu, ps, 4, 8);
            ps += __shfl_down_sync(0xffffffffu, ps, 2, 8);
            ps += __shfl_down_sync(0xffffffffu, ps, 1, 8);
            pd += __shfl_down_sync(0xffffffffu, pd, 4, 8);
            pd += __shfl_down_sync(0xffffffffu, pd, 2, 8);
            pd += __shfl_down_sync(0xffffffffu, pd, 1, 8);
            const int gr = rowBase + tr * TM + i;
            if ((tc & 7) == 0 && gr < M) {
                asrc[gr * H + h] = ps;
                adst[gr * H + h] = pd;
            }
        }
    }
}

// ----------------------------- GAT: one warp per node ------------------------
// Fused segment-softmax + weighted aggregation + bias + relu, no atomics.
__global__ __launch_bounds__(256)
void k_gat(const int* __restrict__ rowptr, const int* __restrict__ csrc,
           const float* __restrict__ xl,
           const float* __restrict__ asrc, const float* __restrict__ adst,
           const float* __restrict__ bias, float* __restrict__ x1, int N) {
    int w = (blockIdx.x * blockDim.x + threadIdx.x) >> 5;
    int lane = threadIdx.x & 31;
    if (w >= N) return;
    const int row = rowptr[w];
    const int end = rowptr[w + 1];

    const int h = lane % H;       // head owned (lanes 0..29)
    const int c = lane / H;       // chunk 0..2 (lanes 0..29)
    const float adst_h = (lane < 30) ? adst[w * H + h] : 0.f;

    // ---- phase 1: per-head max over incoming edges ----
    float m = -FLT_MAX;
    if (lane < 30) {
        for (int i = row + c; i < end; i += 3) {
            int s = csrc[i];
            float a = asrc[s * H + h] + adst_h;
            a = a > 0.f ? a : 0.2f * a;
            m = fmaxf(m, a);
        }
    }
    {
        float mA = __shfl_sync(0xffffffffu, m, lane + 10);
        float mB = __shfl_sync(0xffffffffu, m, lane + 20);
        m = fmaxf(m, fmaxf(mA, mB));     // lanes 0..9 now hold true per-head max
        m = __shfl_sync(0xffffffffu, m, h);  // every lane gets its head's max
    }

    // ---- phase 2: per-head sum of exp ----
    float den = 0.f;
    if (lane < 30) {
        for (int i = row + c; i < end; i += 3) {
            int s = csrc[i];
            float a = asrc[s * H + h] + adst_h;
            a = a > 0.f ? a : 0.2f * a;
            den += __expf(a - m) == __expf(a - m) ? expf(a - m) : 0.f;  // placeholder avoided below
        }
    }
    // NOTE: the line above must be plain expf; rewritten cleanly:
    den = 0.f;
    if (lane < 30) {
        for (int i = row + c; i < end; i += 3) {
            int s = csrc[i];
            float a = asrc[s * H + h] + adst_h;
            a = a > 0.f ? a : 0.2f * a;
            den += expf(a - m);
        }
    }
    {
        float dA = __shfl_sync(0xffffffffu, den, lane + 10);
        float dB = __shfl_sync(0xffffffffu, den, lane + 20);
        den += dA + dB;                 // lanes 0..9 correct
    }
    const float invden = 1.0f / (den + 1e-16f);  // valid on lanes 0..9

    // ---- phase 3: weighted aggregation ----
    float acc[HD / 32];
#pragma unroll
    for (int j = 0; j < HD / 32; j++) acc[j] = 0.f;

    for (int i = row; i < end; i++) {
        int s = csrc[i];  // broadcast load
        float wv = 0.f;
        if (lane < H) {
            float a = asrc[s * H + lane] + adst_h;  // lane<10: h==lane
            a = a > 0.f ? a : 0.2f * a;
            wv = expf(a - m) * invden;
        }
        const float* xs = xl + (size_t)s * HD;
#pragma unroll
        for (int j = 0; j < HD / 32; j++) {
            float wj = __shfl_sync(0xffffffffu, wv, j >> 1);  // head = (32j)/64 = j/2
            acc[j] += xs[lane + 32 * j] * wj;
        }
    }

    float* xo = x1 + (size_t)w * HD;
#pragma unroll
    for (int j = 0; j < HD / 32; j++) {
        int ci = lane + 32 * j;
        xo[ci] = fmaxf(acc[j] + bias[ci], 0.f);   // fused bias + relu
    }
}

// ----------------------------- GCN: one warp per node ------------------------
__global__ __launch_bounds__(256)
void k_gcn(const int* __restrict__ rowptr, const int* __restrict__ csrc,
           const int* __restrict__ cnt, const float* __restrict__ xw,
           const float* __restrict__ bias, float* __restrict__ x2, int N) {
    int w = (blockIdx.x * blockDim.x + threadIdx.x) >> 5;
    int lane = threadIdx.x & 31;
    if (w >= N) return;
    const int row = rowptr[w];
    const int end = rowptr[w + 1];
    const float dn = rsqrtf((float)(end - row));   // in-degree incl self-loop

    float acc[HD / 32];
#pragma unroll
    for (int j = 0; j < HD / 32; j++) acc[j] = 0.f;

    for (int i = row; i < end; i++) {
        int s = csrc[i];
        float nrm = dn * rsqrtf((float)cnt[s]);
        const float* xs = xw + (size_t)s * HD;
#pragma unroll
        for (int j = 0; j < HD / 32; j++)
            acc[j] += xs[lane + 32 * j] * nrm;
    }

    float* xo = x2 + (size_t)w * HD;
#pragma unroll
    for (int j = 0; j < HD / 32; j++) {
        int ci = lane + 32 * j;
        xo[ci] = fmaxf(acc[j] + bias[ci], 0.f);   // fused bias + relu
    }
}

// ----------------------------- pooling ---------------------------------------
__global__ void k_pool(const float* __restrict__ x2, float* __restrict__ pmax,
                       float* __restrict__ psum, int N) {
    int c = threadIdx.x;                         // 640 threads = columns
    float mx = 0.0f, sm = 0.0f;
    for (int n = blockIdx.x; n < N; n += gridDim.x) {
        float v = x2[(size_t)n * HD + c];        // already relu'd (>= 0)
        mx = fmaxf(mx, v);
        sm += v;
    }
    atomicMax((int*)&pmax[c], __float_as_int(mx));   // values >= 0, init 0
    atomicAdd(&psum[c], sm);
}

// ----------------------------- MLP -------------------------------------------
__global__ void k_mlp1(const float* __restrict__ pmax, const float* __restrict__ psum,
                       const float* __restrict__ W1, const float* __restrict__ b1,
                       float* __restrict__ h1, int N) {
    int j = blockIdx.x * blockDim.x + threadIdx.x;
    if (j >= H1DIM) return;
    float acc = b1[j];
    float invN = 1.0f / (float)N;
    for (int k = 0; k < HD; k++)
        acc += pmax[k] * W1[(size_t)k * H1DIM + j];
    for (int k = 0; k < HD; k++)
        acc += psum[k] * invN * W1[(size_t)(HD + k) * H1DIM + j];
    h1[j] = fmaxf(acc, 0.0f);
}

__global__ void k_mlp2(const float* __restrict__ h1, const float* __restrict__ W2,
                       const float* __restrict__ b2, float* __restrict__ out) {
    __shared__ float acc[10];
    int tid = threadIdx.x;
    if (tid < 10) acc[tid] = 0.0f;
    __syncthreads();
    float part[10];
#pragma unroll
    for (int j = 0; j < 10; j++) part[j] = 0.0f;
    for (int k = tid; k < H1DIM; k += 256) {
        float hv = h1[k];
#pragma unroll
        for (int j = 0; j < 10; j++) part[j] += hv * W2[k * 10 + j];
    }
#pragma unroll
    for (int j = 0; j < 10; j++) atomicAdd(&acc[j], part[j]);
    __syncthreads();
    if (tid < 10) out[tid] = acc[tid] + b2[tid];
}

// ----------------------------- launch -----------------------------------------
static inline int cdiv(int a, int b) { return (a + b - 1) / b; }

extern "C" void kernel_launch(void* const* d_in, const int* in_sizes, int n_in,
                              void* d_out, int out_size) {
    const float* x       = (const float*)d_in[0];
    const float* W_gat   = (const float*)d_in[1];
    const float* att_src = (const float*)d_in[2];
    const float* att_dst = (const float*)d_in[3];
    const float* b_gat   = (const float*)d_in[4];
    const float* W_gcn   = (const float*)d_in[5];
    const float* b_gcn   = (const float*)d_in[6];
    const float* W1      = (const float*)d_in[7];
    const float* b1      = (const float*)d_in[8];
    const float* W2      = (const float*)d_in[9];
    const float* b2      = (const float*)d_in[10];
    const int*   ei      = (const int*)d_in[11];

    const int N  = in_sizes[0] / D;
    const int E  = in_sizes[11] / 2;
    const int EP = E + N;
    float* out = (float*)d_out;

    float *p_xl, *p_x1, *p_xw, *p_x2, *p_asrc, *p_adst, *p_pmax, *p_psum, *p_h1;
    int *p_cnt, *p_rowptr, *p_cursor, *p_csrc;
    cudaGetSymbolAddress((void**)&p_xl,     g_xl);
    cudaGetSymbolAddress((void**)&p_x1,     g_x1);
    cudaGetSymbolAddress((void**)&p_xw,     g_xw);
    cudaGetSymbolAddress((void**)&p_x2,     g_x2);
    cudaGetSymbolAddress((void**)&p_asrc,   g_asrc);
    cudaGetSymbolAddress((void**)&p_adst,   g_adst);
    cudaGetSymbolAddress((void**)&p_pmax,   g_pmax);
    cudaGetSymbolAddress((void**)&p_psum,   g_psum);
    cudaGetSymbolAddress((void**)&p_h1,     g_h1);
    cudaGetSymbolAddress((void**)&p_cnt,    g_cnt);
    cudaGetSymbolAddress((void**)&p_rowptr, g_rowptr);
    cudaGetSymbolAddress((void**)&p_cursor, g_cursor);
    cudaGetSymbolAddress((void**)&p_csrc,   g_csrc);

    // 0: init counters + pool accumulators
    k_init<<<cdiv(N + 2 * HD, 256), 256>>>(p_cnt, p_pmax, p_psum, N);
    // 1-3: CSR build
    k_count<<<cdiv(EP, 256), 256>>>(ei, p_cnt, E, N);
    k_scan<<<1, 1024>>>(p_cnt, p_rowptr, p_cursor, N, EP);
    k_scatter<<<cdiv(EP, 256), 256>>>(ei, p_cursor, p_csrc, E, N);
    // 4: GEMM1 (xl = x @ W_gat) + fused attention scores
    k_sgemm<true><<<cdiv(N, BM) * (HD / BN), 256>>>(x, W_gat, p_xl, N, HD, D,
                                                    att_src, att_dst, p_asrc, p_adst);
    // 5: GAT softmax + aggregation (fused, atomics-free)
    k_gat<<<cdiv(N * 32, 256), 256>>>(p_rowptr, p_csrc, p_xl, p_asrc, p_adst,
                                      b_gat, p_x1, N);
    // 6: GEMM2 (xw = x1 @ W_gcn)
    k_sgemm<false><<<cdiv(N, BM) * (HD / BN), 256>>>(p_x1, W_gcn, p_xw, N, HD, HD,
                                                     nullptr, nullptr, nullptr, nullptr);
    // 7: GCN aggregation (atomics-free)
    k_gcn<<<cdiv(N * 32, 256), 256>>>(p_rowptr, p_csrc, p_cnt, p_xw, b_gcn, p_x2, N);
    // 8-10: pool + MLP head
    k_pool<<<256, HD>>>(p_x2, p_pmax, p_psum, N);
    k_mlp1<<<cdiv(H1DIM, 256), 256>>>(p_pmax, p_psum, W1, b1, p_h1, N);
    k_mlp2<<<1, 256>>>(p_h1, W2, b2, out);
}

// round 4
// speedup vs baseline: 1.7876x; 1.4199x over previous
#include <cuda_runtime.h>
#include <float.h>
#include <stdint.h>

// Problem constants (fixed by the dataset)
#define MAXN 20000
#define MAXE 320000
#define MAXEP (MAXE + MAXN)
#define D  64
#define H  10
#define HD 640
#define H1DIM 1500

// ----------------------------- scratch (static, allocation-free) ------------
__device__ __align__(16) float g_xl  [(size_t)MAXN * HD];
__device__ __align__(16) float g_x1  [(size_t)MAXN * HD];
__device__ __align__(16) float g_xw  [(size_t)MAXN * HD];
__device__ __align__(16) float g_x2  [(size_t)MAXN * HD];
__device__ __align__(16) float g_asrc[(size_t)MAXN * H];
__device__ __align__(16) float g_adst[(size_t)MAXN * H];
__device__ __align__(16) float g_pmax[HD];
__device__ __align__(16) float g_psum[HD];
__device__ __align__(16) float g_h1  [H1DIM];
__device__ int g_cnt   [MAXN];
__device__ int g_rowptr[MAXN + 1];
__device__ int g_cursor[MAXN];
__device__ int g_csrc  [MAXEP];

// ----------------------------- init -----------------------------------------
__global__ void k_init(int* __restrict__ cnt, float* __restrict__ pmax,
                       float* __restrict__ psum, int N) {
    int i = blockIdx.x * blockDim.x + threadIdx.x;
    if (i < N) cnt[i] = 0;
    else if (i < N + HD) pmax[i - N] = 0.0f;
    else if (i < N + 2 * HD) psum[i - N - HD] = 0.0f;
}

// ----------------------------- CSR build -------------------------------------
__global__ void k_count(const int* __restrict__ ei, int* __restrict__ cnt, int E, int N) {
    int e = blockIdx.x * blockDim.x + threadIdx.x;
    int EP = E + N;
    if (e >= EP) return;
    int dst = (e < E) ? ei[E + e] : (e - E);
    atomicAdd(&cnt[dst], 1);
}

__global__ __launch_bounds__(1024)
void k_scan(const int* __restrict__ cnt, int* __restrict__ rowptr,
            int* __restrict__ cursor, int N, int EP) {
    __shared__ int sums[1024];
    int t = threadIdx.x;
    int per = (N + 1023) / 1024;
    int start = t * per;
    int end = min(start + per, N);
    int s = 0;
    for (int i = start; i < end; i++) s += cnt[i];
    sums[t] = s;
    __syncthreads();
    int mine = s;
    for (int off = 1; off < 1024; off <<= 1) {
        int o = (t >= off) ? sums[t - off] : 0;
        __syncthreads();
        sums[t] += o;
        __syncthreads();
    }
    int run = sums[t] - mine;
    for (int i = start; i < end; i++) {
        rowptr[i] = run;
        cursor[i] = run;
        run += cnt[i];
    }
    if (t == 0) rowptr[N] = EP;
}

__global__ void k_scatter(const int* __restrict__ ei, int* __restrict__ cursor,
                          int* __restrict__ csrc, int E, int N) {
    int e = blockIdx.x * blockDim.x + threadIdx.x;
    int EP = E + N;
    if (e >= EP) return;
    int src, dst;
    if (e < E) { src = ei[e]; dst = ei[E + e]; }
    else       { src = dst = e - E; }
    int pos = atomicAdd(&cursor[dst], 1);
    csrc[pos] = src;
}

// ----------------------------- SGEMM (fp32, GEMM1 + fused att epilogue) ------
#define BM 128
#define BN 128
#define BK 8
#define TM 8
#define TN 8
template <bool ATT>
__global__ __launch_bounds__(256)
void k_sgemm(const float* __restrict__ A, const float* __restrict__ B,
             float* __restrict__ C, int M, int Nn, int K,
             const float* __restrict__ att_src, const float* __restrict__ att_dst,
             float* __restrict__ asrc, float* __restrict__ adst) {
    __shared__ float As[BK][BM];
    __shared__ float Bs[BK][BN];
    const int tid = threadIdx.x;
    const int nTilesX = Nn / BN;
    const int bx = blockIdx.x % nTilesX;
    const int by = blockIdx.x / nTilesX;
    const int rowBase = by * BM;
    const int colBase = bx * BN;
    const int tr = tid / 16;
    const int tc = tid % 16;

    const int aRow = tid >> 1;
    const int aCol = (tid & 1) * 4;
    const int bRow = tid >> 5;
    const int bCol = (tid & 31) * 4;

    float acc[TM][TN];
#pragma unroll
    for (int i = 0; i < TM; i++)
#pragma unroll
        for (int j = 0; j < TN; j++) acc[i][j] = 0.0f;

    float4 av, bv;
    {
        const int gr = rowBase + aRow;
        if (gr < M) av = *(const float4*)&A[(size_t)gr * K + aCol];
        else        av = make_float4(0.f, 0.f, 0.f, 0.f);
        bv = *(const float4*)&B[(size_t)bRow * Nn + colBase + bCol];
    }

    for (int k0 = 0; k0 < K; k0 += BK) {
        As[aCol + 0][aRow] = av.x;
        As[aCol + 1][aRow] = av.y;
        As[aCol + 2][aRow] = av.z;
        As[aCol + 3][aRow] = av.w;
        *(float4*)&Bs[bRow][bCol] = bv;
        __syncthreads();

        if (k0 + BK < K) {
            const int gr = rowBase + aRow;
            if (gr < M) av = *(const float4*)&A[(size_t)gr * K + k0 + BK + aCol];
            else        av = make_float4(0.f, 0.f, 0.f, 0.f);
            bv = *(const float4*)&B[(size_t)(k0 + BK + bRow) * Nn + colBase + bCol];
        }

#pragma unroll
        for (int k = 0; k < BK; k++) {
            float ar[TM], br[TN];
#pragma unroll
            for (int i = 0; i < TM; i++) ar[i] = As[k][tr * TM + i];
#pragma unroll
            for (int j = 0; j < TN; j++) br[j] = Bs[k][tc * TN + j];
#pragma unroll
            for (int i = 0; i < TM; i++)
#pragma unroll
                for (int j = 0; j < TN; j++) acc[i][j] += ar[i] * br[j];
        }
        __syncthreads();
    }

#pragma unroll
    for (int i = 0; i < TM; i++) {
        const int gr = rowBase + tr * TM + i;
        if (gr < M) {
#pragma unroll
            for (int j = 0; j < TN; j += 4) {
                *(float4*)&C[(size_t)gr * Nn + colBase + tc * TN + j] =
                    make_float4(acc[i][j], acc[i][j + 1], acc[i][j + 2], acc[i][j + 3]);
            }
        }
    }

    if (ATT) {
        const int hloc = tc >> 3;
        const int h = bx * 2 + hloc;
        const int cih = (tc & 7) * 8;
        float as[8], ad[8];
#pragma unroll
        for (int j = 0; j < 8; j++) {
            as[j] = att_src[h * D + cih + j];
            ad[j] = att_dst[h * D + cih + j];
        }
#pragma unroll
        for (int i = 0; i < TM; i++) {
            float ps = 0.f, pd = 0.f;
#pragma unroll
            for (int j = 0; j < TN; j++) { ps += acc[i][j] * as[j]; pd += acc[i][j] * ad[j]; }
            ps += __shfl_down_sync(0xffffffffu, ps, 4, 8);
            ps += __shfl_down_sync(0xffffffffu, ps, 2, 8);
            ps += __shfl_down_sync(0xffffffffu, ps, 1, 8);
            pd += __shfl_down_sync(0xffffffffu, pd, 4, 8);
            pd += __shfl_down_sync(0xffffffffu, pd, 2, 8);
            pd += __shfl_down_sync(0xffffffffu, pd, 1, 8);
            const int gr = rowBase + tr * TM + i;
            if ((tc & 7) == 0 && gr < M) {
                asrc[gr * H + h] = ps;
                adst[gr * H + h] = pd;
            }
        }
    }
}

// ----------------------------- tf32 tensor-core GEMM (GEMM2) ------------------
// C[M,Nn] = A[M,K] @ B[K,Nn], block tile 128x128x16, 8 warps of 32x64.
#define GAPAD 20
#define GBPAD 136
__device__ __forceinline__ uint32_t f2tf32(float x) {
    uint32_t r;
    asm("cvt.rna.tf32.f32 %0, %1;" : "=r"(r) : "f"(x));
    return r;
}

__global__ __launch_bounds__(256)
void k_gemm_tf32(const float* __restrict__ A, const float* __restrict__ B,
                 float* __restrict__ C, int M, int Nn, int K) {
    __shared__ float As[128][GAPAD];
    __shared__ float Bs[16][GBPAD];
    const int tid = threadIdx.x;
    const int warp = tid >> 5, lane = tid & 31;
    const int wm = warp & 3, wn = warp >> 2;        // 4 x 2 warp grid
    const int nTilesX = Nn / 128;
    const int bx = blockIdx.x % nTilesX;
    const int by = blockIdx.x / nTilesX;
    const int rowBase = by * 128, colBase = bx * 128;

    const int gID = lane >> 2;       // group id 0..7
    const int tIG = lane & 3;        // thread-in-group 0..3

    float acc[2][8][4];
#pragma unroll
    for (int mt = 0; mt < 2; mt++)
#pragma unroll
        for (int nt = 0; nt < 8; nt++)
#pragma unroll
            for (int r = 0; r < 4; r++) acc[mt][nt][r] = 0.0f;

    const int aR  = tid >> 2;        // 0..63
    const int aC4 = (tid & 3) * 4;   // 0,4,8,12
    const int bR  = tid >> 5;        // 0..7
    const int bC4 = lane * 4;        // 0..124

    for (int k0 = 0; k0 < K; k0 += 16) {
        // stage A (rows aR, aR+64), convert to tf32 once
#pragma unroll
        for (int half = 0; half < 2; half++) {
            int r = aR + half * 64;
            int gr = rowBase + r;
            float4 v = (gr < M) ? *(const float4*)&A[(size_t)gr * K + k0 + aC4]
                                : make_float4(0.f, 0.f, 0.f, 0.f);
            As[r][aC4 + 0] = __uint_as_float(f2tf32(v.x));
            As[r][aC4 + 1] = __uint_as_float(f2tf32(v.y));
            As[r][aC4 + 2] = __uint_as_float(f2tf32(v.z));
            As[r][aC4 + 3] = __uint_as_float(f2tf32(v.w));
        }
        // stage B (rows bR, bR+8)
#pragma unroll
        for (int half = 0; half < 2; half++) {
            int r = bR + half * 8;
            float4 v = *(const float4*)&B[(size_t)(k0 + r) * Nn + colBase + bC4];
            Bs[r][bC4 + 0] = __uint_as_float(f2tf32(v.x));
            Bs[r][bC4 + 1] = __uint_as_float(f2tf32(v.y));
            Bs[r][bC4 + 2] = __uint_as_float(f2tf32(v.z));
            Bs[r][bC4 + 3] = __uint_as_float(f2tf32(v.w));
        }
        __syncthreads();

#pragma unroll
        for (int ks = 0; ks < 16; ks += 8) {
            uint32_t af[2][4];
#pragma unroll
            for (int mt = 0; mt < 2; mt++) {
                int r0 = wm * 32 + mt * 16 + gID;
                int kc = ks + tIG;
                af[mt][0] = __float_as_uint(As[r0][kc]);
                af[mt][1] = __float_as_uint(As[r0 + 8][kc]);
                af[mt][2] = __float_as_uint(As[r0][kc + 4]);
                af[mt][3] = __float_as_uint(As[r0 + 8][kc + 4]);
            }
#pragma unroll
            for (int nt = 0; nt < 8; nt++) {
                int col = wn * 64 + nt * 8 + gID;
                uint32_t b0 = __float_as_uint(Bs[ks + tIG][col]);
                uint32_t b1 = __float_as_uint(Bs[ks + tIG + 4][col]);
#pragma unroll
                for (int mt = 0; mt < 2; mt++) {
                    asm volatile(
                        "mma.sync.aligned.m16n8k8.row.col.f32.tf32.tf32.f32 "
                        "{%0,%1,%2,%3}, {%4,%5,%6,%7}, {%8,%9}, {%0,%1,%2,%3};\n"
                        : "+f"(acc[mt][nt][0]), "+f"(acc[mt][nt][1]),
                          "+f"(acc[mt][nt][2]), "+f"(acc[mt][nt][3])
                        : "r"(af[mt][0]), "r"(af[mt][1]), "r"(af[mt][2]), "r"(af[mt][3]),
                          "r"(b0), "r"(b1));
                }
            }
        }
        __syncthreads();
    }

    // epilogue
#pragma unroll
    for (int mt = 0; mt < 2; mt++) {
        int r0 = rowBase + wm * 32 + mt * 16 + gID;
#pragma unroll
        for (int nt = 0; nt < 8; nt++) {
            int c0 = colBase + wn * 64 + nt * 8 + tIG * 2;
            if (r0 < M)
                *(float2*)&C[(size_t)r0 * Nn + c0] = make_float2(acc[mt][nt][0], acc[mt][nt][1]);
            if (r0 + 8 < M)
                *(float2*)&C[(size_t)(r0 + 8) * Nn + c0] = make_float2(acc[mt][nt][2], acc[mt][nt][3]);
        }
    }
}

// ----------------------------- GAT: one warp per node ------------------------
__global__ __launch_bounds__(256)
void k_gat(const int* __restrict__ rowptr, const int* __restrict__ csrc,
           const float* __restrict__ xl,
           const float* __restrict__ asrc, const float* __restrict__ adst,
           const float* __restrict__ bias, float* __restrict__ x1, int N) {
    int w = (blockIdx.x * blockDim.x + threadIdx.x) >> 5;
    int lane = threadIdx.x & 31;
    if (w >= N) return;
    const int row = rowptr[w];
    const int end = rowptr[w + 1];

    const int h = lane % H;
    const int c = lane / H;
    const float adst_h = (lane < 30) ? adst[w * H + h] : 0.f;

    // phase 1: per-head max
    float m = -FLT_MAX;
    if (lane < 30) {
        for (int i = row + c; i < end; i += 3) {
            int s = csrc[i];
            float a = asrc[s * H + h] + adst_h;
            a = a > 0.f ? a : 0.2f * a;
            m = fmaxf(m, a);
        }
    }
    {
        float mA = __shfl_sync(0xffffffffu, m, lane + 10);
        float mB = __shfl_sync(0xffffffffu, m, lane + 20);
        m = fmaxf(m, fmaxf(mA, mB));
        m = __shfl_sync(0xffffffffu, m, h);
    }

    // phase 2: per-head sum of exp
    float den = 0.f;
    if (lane < 30) {
        for (int i = row + c; i < end; i += 3) {
            int s = csrc[i];
            float a = asrc[s * H + h] + adst_h;
            a = a > 0.f ? a : 0.2f * a;
            den += expf(a - m);
        }
    }
    {
        float dA = __shfl_sync(0xffffffffu, den, lane + 10);
        float dB = __shfl_sync(0xffffffffu, den, lane + 20);
        den += dA + dB;
    }
    const float invden = 1.0f / (den + 1e-16f);

    // phase 3: weighted aggregation
    float acc[HD / 32];
#pragma unroll
    for (int j = 0; j < HD / 32; j++) acc[j] = 0.f;

    for (int i = row; i < end; i++) {
        int s = csrc[i];
        float wv = 0.f;
        if (lane < H) {
            float a = asrc[s * H + lane] + adst_h;
            a = a > 0.f ? a : 0.2f * a;
            wv = expf(a - m) * invden;
        }
        const float* xs = xl + (size_t)s * HD;
#pragma unroll
        for (int j = 0; j < HD / 32; j++) {
            float wj = __shfl_sync(0xffffffffu, wv, j >> 1);
            acc[j] += xs[lane + 32 * j] * wj;
        }
    }

    float* xo = x1 + (size_t)w * HD;
#pragma unroll
    for (int j = 0; j < HD / 32; j++) {
        int ci = lane + 32 * j;
        xo[ci] = fmaxf(acc[j] + bias[ci], 0.f);
    }
}

// ----------------------------- GCN: one warp per node ------------------------
__global__ __launch_bounds__(256)
void k_gcn(const int* __restrict__ rowptr, const int* __restrict__ csrc,
           const int* __restrict__ cnt, const float* __restrict__ xw,
           const float* __restrict__ bias, float* __restrict__ x2, int N) {
    int w = (blockIdx.x * blockDim.x + threadIdx.x) >> 5;
    int lane = threadIdx.x & 31;
    if (w >= N) return;
    const int row = rowptr[w];
    const int end = rowptr[w + 1];
    const float dn = rsqrtf((float)(end - row));

    float acc[HD / 32];
#pragma unroll
    for (int j = 0; j < HD / 32; j++) acc[j] = 0.f;

    for (int i = row; i < end; i++) {
        int s = csrc[i];
        float nrm = dn * rsqrtf((float)cnt[s]);
        const float* xs = xw + (size_t)s * HD;
#pragma unroll
        for (int j = 0; j < HD / 32; j++)
            acc[j] += xs[lane + 32 * j] * nrm;
    }

    float* xo = x2 + (size_t)w * HD;
#pragma unroll
    for (int j = 0; j < HD / 32; j++) {
        int ci = lane + 32 * j;
        xo[ci] = fmaxf(acc[j] + bias[ci], 0.f);
    }
}

// ----------------------------- pooling ---------------------------------------
__global__ void k_pool(const float* __restrict__ x2, float* __restrict__ pmax,
                       float* __restrict__ psum, int N) {
    int c = threadIdx.x;
    float mx = 0.0f, sm = 0.0f;
    for (int n = blockIdx.x; n < N; n += gridDim.x) {
        float v = x2[(size_t)n * HD + c];
        mx = fmaxf(mx, v);
        sm += v;
    }
    atomicMax((int*)&pmax[c], __float_as_int(mx));
    atomicAdd(&psum[c], sm);
}

// ----------------------------- MLP -------------------------------------------
__global__ void k_mlp1(const float* __restrict__ pmax, const float* __restrict__ psum,
                       const float* __restrict__ W1, const float* __restrict__ b1,
                       float* __restrict__ h1, int N) {
    int j = blockIdx.x * blockDim.x + threadIdx.x;
    if (j >= H1DIM) return;
    float acc = b1[j];
    float invN = 1.0f / (float)N;
    for (int k = 0; k < HD; k++)
        acc += pmax[k] * W1[(size_t)k * H1DIM + j];
    for (int k = 0; k < HD; k++)
        acc += psum[k] * invN * W1[(size_t)(HD + k) * H1DIM + j];
    h1[j] = fmaxf(acc, 0.0f);
}

__global__ void k_mlp2(const float* __restrict__ h1, const float* __restrict__ W2,
                       const float* __restrict__ b2, float* __restrict__ out) {
    __shared__ float acc[10];
    int tid = threadIdx.x;
    if (tid < 10) acc[tid] = 0.0f;
    __syncthreads();
    float part[10];
#pragma unroll
    for (int j = 0; j < 10; j++) part[j] = 0.0f;
    for (int k = tid; k < H1DIM; k += 256) {
        float hv = h1[k];
#pragma unroll
        for (int j = 0; j < 10; j++) part[j] += hv * W2[k * 10 + j];
    }
#pragma unroll
    for (int j = 0; j < 10; j++) atomicAdd(&acc[j], part[j]);
    __syncthreads();
    if (tid < 10) out[tid] = acc[tid] + b2[tid];
}

// ----------------------------- launch -----------------------------------------
static inline int cdiv(int a, int b) { return (a + b - 1) / b; }

extern "C" void kernel_launch(void* const* d_in, const int* in_sizes, int n_in,
                              void* d_out, int out_size) {
    const float* x       = (const float*)d_in[0];
    const float* W_gat   = (const float*)d_in[1];
    const float* att_src = (const float*)d_in[2];
    const float* att_dst = (const float*)d_in[3];
    const float* b_gat   = (const float*)d_in[4];
    const float* W_gcn   = (const float*)d_in[5];
    const float* b_gcn   = (const float*)d_in[6];
    const float* W1      = (const float*)d_in[7];
    const float* b1      = (const float*)d_in[8];
    const float* W2      = (const float*)d_in[9];
    const float* b2      = (const float*)d_in[10];
    const int*   ei      = (const int*)d_in[11];

    const int N  = in_sizes[0] / D;
    const int E  = in_sizes[11] / 2;
    const int EP = E + N;
    float* out = (float*)d_out;

    float *p_xl, *p_x1, *p_xw, *p_x2, *p_asrc, *p_adst, *p_pmax, *p_psum, *p_h1;
    int *p_cnt, *p_rowptr, *p_cursor, *p_csrc;
    cudaGetSymbolAddress((void**)&p_xl,     g_xl);
    cudaGetSymbolAddress((void**)&p_x1,     g_x1);
    cudaGetSymbolAddress((void**)&p_xw,     g_xw);
    cudaGetSymbolAddress((void**)&p_x2,     g_x2);
    cudaGetSymbolAddress((void**)&p_asrc,   g_asrc);
    cudaGetSymbolAddress((void**)&p_adst,   g_adst);
    cudaGetSymbolAddress((void**)&p_pmax,   g_pmax);
    cudaGetSymbolAddress((void**)&p_psum,   g_psum);
    cudaGetSymbolAddress((void**)&p_h1,     g_h1);
    cudaGetSymbolAddress((void**)&p_cnt,    g_cnt);
    cudaGetSymbolAddress((void**)&p_rowptr, g_rowptr);
    cudaGetSymbolAddress((void**)&p_cursor, g_cursor);
    cudaGetSymbolAddress((void**)&p_csrc,   g_csrc);

    // init + CSR build
    k_init<<<cdiv(N + 2 * HD, 256), 256>>>(p_cnt, p_pmax, p_psum, N);
    k_count<<<cdiv(EP, 256), 256>>>(ei, p_cnt, E, N);
    k_scan<<<1, 1024>>>(p_cnt, p_rowptr, p_cursor, N, EP);
    k_scatter<<<cdiv(EP, 256), 256>>>(ei, p_cursor, p_csrc, E, N);
    // GEMM1 (fp32) + fused attention scores
    k_sgemm<true><<<cdiv(N, BM) * (HD / BN), 256>>>(x, W_gat, p_xl, N, HD, D,
                                                    att_src, att_dst, p_asrc, p_adst);
    // GAT softmax + aggregation
    k_gat<<<cdiv(N * 32, 256), 256>>>(p_rowptr, p_csrc, p_xl, p_asrc, p_adst,
                                      b_gat, p_x1, N);
    // GEMM2: tf32 tensor cores
    k_gemm_tf32<<<cdiv(N, 128) * (HD / 128), 256>>>(p_x1, W_gcn, p_xw, N, HD, HD);
    // GCN aggregation
    k_gcn<<<cdiv(N * 32, 256), 256>>>(p_rowptr, p_csrc, p_cnt, p_xw, b_gcn, p_x2, N);
    // pool + MLP head
    k_pool<<<256, HD>>>(p_x2, p_pmax, p_psum, N);
    k_mlp1<<<cdiv(H1DIM, 256), 256>>>(p_pmax, p_psum, W1, b1, p_h1, N);
    k_mlp2<<<1, 256>>>(p_h1, W2, b2, out);
}

// round 5
// speedup vs baseline: 2.0982x; 1.1738x over previous
#include <cuda_runtime.h>
#include <float.h>
#include <stdint.h>

// Problem constants (fixed by the dataset)
#define MAXN 20000
#define MAXE 320000
#define MAXEP (MAXE + MAXN)
#define D  64
#define H  10
#define HD 640
#define H1DIM 1500

// ----------------------------- scratch (static, allocation-free) ------------
__device__ __align__(16) float g_xl  [(size_t)MAXN * HD];
__device__ __align__(16) float g_x1  [(size_t)MAXN * HD];
__device__ __align__(16) float g_xw  [(size_t)MAXN * HD];
__device__ __align__(16) float g_asrc[(size_t)MAXN * H];
__device__ __align__(16) float g_adst[(size_t)MAXN * H];
__device__ __align__(16) float g_pmax[HD];
__device__ __align__(16) float g_psum[HD];
__device__ __align__(16) float g_h1  [H1DIM];
__device__ int g_cnt   [MAXN];
__device__ int g_rowptr[MAXN + 1];
__device__ int g_cursor[MAXN];
__device__ int g_csrc  [MAXEP];

// ----------------------------- init -----------------------------------------
__global__ void k_init(int* __restrict__ cnt, float* __restrict__ pmax,
                       float* __restrict__ psum, int N) {
    int i = blockIdx.x * blockDim.x + threadIdx.x;
    if (i < N) cnt[i] = 0;
    else if (i < N + HD) pmax[i - N] = 0.0f;
    else if (i < N + 2 * HD) psum[i - N - HD] = 0.0f;
}

// ----------------------------- CSR build -------------------------------------
__global__ void k_count(const int* __restrict__ ei, int* __restrict__ cnt, int E, int N) {
    int e = blockIdx.x * blockDim.x + threadIdx.x;
    int EP = E + N;
    if (e >= EP) return;
    int dst = (e < E) ? ei[E + e] : (e - E);
    atomicAdd(&cnt[dst], 1);
}

__global__ __launch_bounds__(1024)
void k_scan(const int* __restrict__ cnt, int* __restrict__ rowptr,
            int* __restrict__ cursor, int N, int EP) {
    __shared__ int sums[1024];
    int t = threadIdx.x;
    int per = (N + 1023) / 1024;
    int start = t * per;
    int end = min(start + per, N);
    int s = 0;
    for (int i = start; i < end; i++) s += cnt[i];
    sums[t] = s;
    __syncthreads();
    int mine = s;
    for (int off = 1; off < 1024; off <<= 1) {
        int o = (t >= off) ? sums[t - off] : 0;
        __syncthreads();
        sums[t] += o;
        __syncthreads();
    }
    int run = sums[t] - mine;
    for (int i = start; i < end; i++) {
        rowptr[i] = run;
        cursor[i] = run;
        run += cnt[i];
    }
    if (t == 0) rowptr[N] = EP;
}

__global__ void k_scatter(const int* __restrict__ ei, int* __restrict__ cursor,
                          int* __restrict__ csrc, int E, int N) {
    int e = blockIdx.x * blockDim.x + threadIdx.x;
    int EP = E + N;
    if (e >= EP) return;
    int src, dst;
    if (e < E) { src = ei[e]; dst = ei[E + e]; }
    else       { src = dst = e - E; }
    int pos = atomicAdd(&cursor[dst], 1);
    csrc[pos] = src;
}

// ----------------------------- SGEMM (fp32, GEMM1 + fused att epilogue) ------
#define BM 128
#define BN 128
#define BK 8
#define TM 8
#define TN 8
template <bool ATT>
__global__ __launch_bounds__(256)
void k_sgemm(const float* __restrict__ A, const float* __restrict__ B,
             float* __restrict__ C, int M, int Nn, int K,
             const float* __restrict__ att_src, const float* __restrict__ att_dst,
             float* __restrict__ asrc, float* __restrict__ adst) {
    __shared__ float As[BK][BM];
    __shared__ float Bs[BK][BN];
    const int tid = threadIdx.x;
    const int nTilesX = Nn / BN;
    const int bx = blockIdx.x % nTilesX;
    const int by = blockIdx.x / nTilesX;
    const int rowBase = by * BM;
    const int colBase = bx * BN;
    const int tr = tid / 16;
    const int tc = tid % 16;

    const int aRow = tid >> 1;
    const int aCol = (tid & 1) * 4;
    const int bRow = tid >> 5;
    const int bCol = (tid & 31) * 4;

    float acc[TM][TN];
#pragma unroll
    for (int i = 0; i < TM; i++)
#pragma unroll
        for (int j = 0; j < TN; j++) acc[i][j] = 0.0f;

    float4 av, bv;
    {
        const int gr = rowBase + aRow;
        if (gr < M) av = *(const float4*)&A[(size_t)gr * K + aCol];
        else        av = make_float4(0.f, 0.f, 0.f, 0.f);
        bv = *(const float4*)&B[(size_t)bRow * Nn + colBase + bCol];
    }

    for (int k0 = 0; k0 < K; k0 += BK) {
        As[aCol + 0][aRow] = av.x;
        As[aCol + 1][aRow] = av.y;
        As[aCol + 2][aRow] = av.z;
        As[aCol + 3][aRow] = av.w;
        *(float4*)&Bs[bRow][bCol] = bv;
        __syncthreads();

        if (k0 + BK < K) {
            const int gr = rowBase + aRow;
            if (gr < M) av = *(const float4*)&A[(size_t)gr * K + k0 + BK + aCol];
            else        av = make_float4(0.f, 0.f, 0.f, 0.f);
            bv = *(const float4*)&B[(size_t)(k0 + BK + bRow) * Nn + colBase + bCol];
        }

#pragma unroll
        for (int k = 0; k < BK; k++) {
            float ar[TM], br[TN];
#pragma unroll
            for (int i = 0; i < TM; i++) ar[i] = As[k][tr * TM + i];
#pragma unroll
            for (int j = 0; j < TN; j++) br[j] = Bs[k][tc * TN + j];
#pragma unroll
            for (int i = 0; i < TM; i++)
#pragma unroll
                for (int j = 0; j < TN; j++) acc[i][j] += ar[i] * br[j];
        }
        __syncthreads();
    }

#pragma unroll
    for (int i = 0; i < TM; i++) {
        const int gr = rowBase + tr * TM + i;
        if (gr < M) {
#pragma unroll
            for (int j = 0; j < TN; j += 4) {
                *(float4*)&C[(size_t)gr * Nn + colBase + tc * TN + j] =
                    make_float4(acc[i][j], acc[i][j + 1], acc[i][j + 2], acc[i][j + 3]);
            }
        }
    }

    if (ATT) {
        const int hloc = tc >> 3;
        const int h = bx * 2 + hloc;
        const int cih = (tc & 7) * 8;
        float as[8], ad[8];
#pragma unroll
        for (int j = 0; j < 8; j++) {
            as[j] = att_src[h * D + cih + j];
            ad[j] = att_dst[h * D + cih + j];
        }
#pragma unroll
        for (int i = 0; i < TM; i++) {
            float ps = 0.f, pd = 0.f;
#pragma unroll
            for (int j = 0; j < TN; j++) { ps += acc[i][j] * as[j]; pd += acc[i][j] * ad[j]; }
            ps += __shfl_down_sync(0xffffffffu, ps, 4, 8);
            ps += __shfl_down_sync(0xffffffffu, ps, 2, 8);
            ps += __shfl_down_sync(0xffffffffu, ps, 1, 8);
            pd += __shfl_down_sync(0xffffffffu, pd, 4, 8);
            pd += __shfl_down_sync(0xffffffffu, pd, 2, 8);
            pd += __shfl_down_sync(0xffffffffu, pd, 1, 8);
            const int gr = rowBase + tr * TM + i;
            if ((tc & 7) == 0 && gr < M) {
                asrc[gr * H + h] = ps;
                adst[gr * H + h] = pd;
            }
        }
    }
}

// ----------------------------- tf32 tensor-core GEMM (GEMM2, double-buffered) --
#define GAPAD 20
#define GBPAD 136
__device__ __forceinline__ uint32_t f2tf32(float x) {
    uint32_t r;
    asm("cvt.rna.tf32.f32 %0, %1;" : "=r"(r) : "f"(x));
    return r;
}

__global__ __launch_bounds__(256)
void k_gemm_tf32(const float* __restrict__ A, const float* __restrict__ B,
                 float* __restrict__ C, int M, int Nn, int K) {
    __shared__ float As[2][128][GAPAD];
    __shared__ float Bs[2][16][GBPAD];
    const int tid = threadIdx.x;
    const int warp = tid >> 5, lane = tid & 31;
    const int wm = warp & 3, wn = warp >> 2;        // 4 x 2 warp grid
    const int nTilesX = Nn / 128;
    const int bx = blockIdx.x % nTilesX;
    const int by = blockIdx.x / nTilesX;
    const int rowBase = by * 128, colBase = bx * 128;

    const int gID = lane >> 2;
    const int tIG = lane & 3;

    float acc[2][8][4];
#pragma unroll
    for (int mt = 0; mt < 2; mt++)
#pragma unroll
        for (int nt = 0; nt < 8; nt++)
#pragma unroll
            for (int r = 0; r < 4; r++) acc[mt][nt][r] = 0.0f;

    const int aR  = tid >> 2;
    const int aC4 = (tid & 3) * 4;
    const int bR  = tid >> 5;
    const int bC4 = lane * 4;

    float4 avr[2], bvr[2];
    // initial loads (k0 = 0)
#pragma unroll
    for (int half = 0; half < 2; half++) {
        int gr = rowBase + aR + half * 64;
        avr[half] = (gr < M) ? *(const float4*)&A[(size_t)gr * K + aC4]
                             : make_float4(0.f, 0.f, 0.f, 0.f);
        bvr[half] = *(const float4*)&B[(size_t)(bR + half * 8) * Nn + colBase + bC4];
    }

    int buf = 0;
    for (int k0 = 0; k0 < K; k0 += 16) {
        // stage current tile (convert to tf32 once)
#pragma unroll
        for (int half = 0; half < 2; half++) {
            int r = aR + half * 64;
            As[buf][r][aC4 + 0] = __uint_as_float(f2tf32(avr[half].x));
            As[buf][r][aC4 + 1] = __uint_as_float(f2tf32(avr[half].y));
            As[buf][r][aC4 + 2] = __uint_as_float(f2tf32(avr[half].z));
            As[buf][r][aC4 + 3] = __uint_as_float(f2tf32(avr[half].w));
            int rb = bR + half * 8;
            Bs[buf][rb][bC4 + 0] = __uint_as_float(f2tf32(bvr[half].x));
            Bs[buf][rb][bC4 + 1] = __uint_as_float(f2tf32(bvr[half].y));
            Bs[buf][rb][bC4 + 2] = __uint_as_float(f2tf32(bvr[half].z));
            Bs[buf][rb][bC4 + 3] = __uint_as_float(f2tf32(bvr[half].w));
        }
        __syncthreads();

        // prefetch next tile into registers
        if (k0 + 16 < K) {
#pragma unroll
            for (int half = 0; half < 2; half++) {
                int gr = rowBase + aR + half * 64;
                avr[half] = (gr < M) ? *(const float4*)&A[(size_t)gr * K + k0 + 16 + aC4]
                                     : make_float4(0.f, 0.f, 0.f, 0.f);
                bvr[half] = *(const float4*)&B[(size_t)(k0 + 16 + bR + half * 8) * Nn + colBase + bC4];
            }
        }

#pragma unroll
        for (int ks = 0; ks < 16; ks += 8) {
            uint32_t af[2][4];
#pragma unroll
            for (int mt = 0; mt < 2; mt++) {
                int r0 = wm * 32 + mt * 16 + gID;
                int kc = ks + tIG;
                af[mt][0] = __float_as_uint(As[buf][r0][kc]);
                af[mt][1] = __float_as_uint(As[buf][r0 + 8][kc]);
                af[mt][2] = __float_as_uint(As[buf][r0][kc + 4]);
                af[mt][3] = __float_as_uint(As[buf][r0 + 8][kc + 4]);
            }
#pragma unroll
            for (int nt = 0; nt < 8; nt++) {
                int col = wn * 64 + nt * 8 + gID;
                uint32_t b0 = __float_as_uint(Bs[buf][ks + tIG][col]);
                uint32_t b1 = __float_as_uint(Bs[buf][ks + tIG + 4][col]);
#pragma unroll
                for (int mt = 0; mt < 2; mt++) {
                    asm volatile(
                        "mma.sync.aligned.m16n8k8.row.col.f32.tf32.tf32.f32 "
                        "{%0,%1,%2,%3}, {%4,%5,%6,%7}, {%8,%9}, {%0,%1,%2,%3};\n"
                        : "+f"(acc[mt][nt][0]), "+f"(acc[mt][nt][1]),
                          "+f"(acc[mt][nt][2]), "+f"(acc[mt][nt][3])
                        : "r"(af[mt][0]), "r"(af[mt][1]), "r"(af[mt][2]), "r"(af[mt][3]),
                          "r"(b0), "r"(b1));
                }
            }
        }
        buf ^= 1;
    }

#pragma unroll
    for (int mt = 0; mt < 2; mt++) {
        int r0 = rowBase + wm * 32 + mt * 16 + gID;
#pragma unroll
        for (int nt = 0; nt < 8; nt++) {
            int c0 = colBase + wn * 64 + nt * 8 + tIG * 2;
            if (r0 < M)
                *(float2*)&C[(size_t)r0 * Nn + c0] = make_float2(acc[mt][nt][0], acc[mt][nt][1]);
            if (r0 + 8 < M)
                *(float2*)&C[(size_t)(r0 + 8) * Nn + c0] = make_float2(acc[mt][nt][2], acc[mt][nt][3]);
        }
    }
}

// ----------------------------- GAT: one warp per node (float4) ---------------
__global__ __launch_bounds__(256)
void k_gat(const int* __restrict__ rowptr, const int* __restrict__ csrc,
           const float* __restrict__ xl,
           const float* __restrict__ asrc, const float* __restrict__ adst,
           const float* __restrict__ bias, float* __restrict__ x1, int N) {
    int w = (blockIdx.x * blockDim.x + threadIdx.x) >> 5;
    int lane = threadIdx.x & 31;
    if (w >= N) return;
    const int row = rowptr[w];
    const int end = rowptr[w + 1];

    const int h = lane % H;
    const int c = lane / H;
    const float adst_h = (lane < 30) ? adst[w * H + h] : 0.f;

    // phase 1: per-head max
    float m = -FLT_MAX;
    if (lane < 30) {
        for (int i = row + c; i < end; i += 3) {
            int s = csrc[i];
            float a = asrc[s * H + h] + adst_h;
            a = a > 0.f ? a : 0.2f * a;
            m = fmaxf(m, a);
        }
    }
    {
        float mA = __shfl_sync(0xffffffffu, m, lane + 10);
        float mB = __shfl_sync(0xffffffffu, m, lane + 20);
        m = fmaxf(m, fmaxf(mA, mB));
        m = __shfl_sync(0xffffffffu, m, h);
    }

    // phase 2: per-head sum of exp
    float den = 0.f;
    if (lane < 30) {
        for (int i = row + c; i < end; i += 3) {
            int s = csrc[i];
            float a = asrc[s * H + h] + adst_h;
            a = a > 0.f ? a : 0.2f * a;
            den += expf(a - m);
        }
    }
    {
        float dA = __shfl_sync(0xffffffffu, den, lane + 10);
        float dB = __shfl_sync(0xffffffffu, den, lane + 20);
        den += dA + dB;
    }
    const float invden = 1.0f / (den + 1e-16f);

    // phase 3: weighted aggregation (float4)
    float4 acc4[5];
#pragma unroll
    for (int j = 0; j < 5; j++) acc4[j] = make_float4(0.f, 0.f, 0.f, 0.f);

    const int hsel = lane >> 4;   // float4 at col 4*lane+128j belongs to head 2j + (lane>=16)
    for (int i = row; i < end; i++) {
        int s = csrc[i];
        float wv = 0.f;
        if (lane < H) {
            float a = asrc[s * H + lane] + adst_h;
            a = a > 0.f ? a : 0.2f * a;
            wv = expf(a - m) * invden;
        }
        const float4* xs4 = (const float4*)(xl + (size_t)s * HD);
#pragma unroll
        for (int j = 0; j < 5; j++) {
            float wj = __shfl_sync(0xffffffffu, wv, 2 * j + hsel);
            float4 v = xs4[lane + 32 * j];
            acc4[j].x += v.x * wj;
            acc4[j].y += v.y * wj;
            acc4[j].z += v.z * wj;
            acc4[j].w += v.w * wj;
        }
    }

    float4* xo4 = (float4*)(x1 + (size_t)w * HD);
    const float4* b4 = (const float4*)bias;
#pragma unroll
    for (int j = 0; j < 5; j++) {
        int idx = lane + 32 * j;
        float4 bb = b4[idx];
        float4 v = acc4[j];
        v.x = fmaxf(v.x + bb.x, 0.f);
        v.y = fmaxf(v.y + bb.y, 0.f);
        v.z = fmaxf(v.z + bb.z, 0.f);
        v.w = fmaxf(v.w + bb.w, 0.f);
        xo4[idx] = v;
    }
}

// ----------------------------- GCN + fused global pooling --------------------
// One warp per node; block-level smem reduction of max/sum, then one global
// atomic per column per block. x2 is never materialized.
__global__ __launch_bounds__(256)
void k_gcn_pool(const int* __restrict__ rowptr, const int* __restrict__ csrc,
                const int* __restrict__ cnt, const float* __restrict__ xw,
                const float* __restrict__ bias,
                float* __restrict__ pmax, float* __restrict__ psum, int N) {
    __shared__ float smax[HD];
    __shared__ float ssum[HD];
    const int tid = threadIdx.x;
    for (int i = tid; i < HD; i += 256) { smax[i] = 0.f; ssum[i] = 0.f; }
    __syncthreads();

    const int w = (blockIdx.x * blockDim.x + tid) >> 5;
    const int lane = tid & 31;

    if (w < N) {
        const int row = rowptr[w];
        const int end = rowptr[w + 1];
        const float dn = rsqrtf((float)(end - row));

        float4 acc4[5];
#pragma unroll
        for (int j = 0; j < 5; j++) acc4[j] = make_float4(0.f, 0.f, 0.f, 0.f);

        for (int i = row; i < end; i++) {
            int s = csrc[i];
            float nrm = dn * rsqrtf((float)cnt[s]);
            const float4* xs4 = (const float4*)(xw + (size_t)s * HD);
#pragma unroll
            for (int j = 0; j < 5; j++) {
                float4 v = xs4[lane + 32 * j];
                acc4[j].x += v.x * nrm;
                acc4[j].y += v.y * nrm;
                acc4[j].z += v.z * nrm;
                acc4[j].w += v.w * nrm;
            }
        }

        const float4* b4 = (const float4*)bias;
#pragma unroll
        for (int j = 0; j < 5; j++) {
            int idx = lane + 32 * j;       // float4 index; col = 4*idx
            float4 bb = b4[idx];
            float4 v = acc4[j];
            v.x = fmaxf(v.x + bb.x, 0.f);
            v.y = fmaxf(v.y + bb.y, 0.f);
            v.z = fmaxf(v.z + bb.z, 0.f);
            v.w = fmaxf(v.w + bb.w, 0.f);
            int col = idx * 4;
            atomicMax((int*)&smax[col + 0], __float_as_int(v.x));
            atomicMax((int*)&smax[col + 1], __float_as_int(v.y));
            atomicMax((int*)&smax[col + 2], __float_as_int(v.z));
            atomicMax((int*)&smax[col + 3], __float_as_int(v.w));
            atomicAdd(&ssum[col + 0], v.x);
            atomicAdd(&ssum[col + 1], v.y);
            atomicAdd(&ssum[col + 2], v.z);
            atomicAdd(&ssum[col + 3], v.w);
        }
    }
    __syncthreads();

    for (int i = tid; i < HD; i += 256) {
        atomicMax((int*)&pmax[i], __float_as_int(smax[i]));
        atomicAdd(&psum[i], ssum[i]);
    }
}

// ----------------------------- MLP -------------------------------------------
__global__ void k_mlp1(const float* __restrict__ pmax, const float* __restrict__ psum,
                       const float* __restrict__ W1, const float* __restrict__ b1,
                       float* __restrict__ h1, int N) {
    int j = blockIdx.x * blockDim.x + threadIdx.x;
    if (j >= H1DIM) return;
    float acc = b1[j];
    float invN = 1.0f / (float)N;
    for (int k = 0; k < HD; k++)
        acc += pmax[k] * W1[(size_t)k * H1DIM + j];
    for (int k = 0; k < HD; k++)
        acc += psum[k] * invN * W1[(size_t)(HD + k) * H1DIM + j];
    h1[j] = fmaxf(acc, 0.0f);
}

__global__ void k_mlp2(const float* __restrict__ h1, const float* __restrict__ W2,
                       const float* __restrict__ b2, float* __restrict__ out) {
    __shared__ float acc[10];
    int tid = threadIdx.x;
    if (tid < 10) acc[tid] = 0.0f;
    __syncthreads();
    float part[10];
#pragma unroll
    for (int j = 0; j < 10; j++) part[j] = 0.0f;
    for (int k = tid; k < H1DIM; k += 256) {
        float hv = h1[k];
#pragma unroll
        for (int j = 0; j < 10; j++) part[j] += hv * W2[k * 10 + j];
    }
#pragma unroll
    for (int j = 0; j < 10; j++) atomicAdd(&acc[j], part[j]);
    __syncthreads();
    if (tid < 10) out[tid] = acc[tid] + b2[tid];
}

// ----------------------------- launch -----------------------------------------
static inline int cdiv(int a, int b) { return (a + b - 1) / b; }

extern "C" void kernel_launch(void* const* d_in, const int* in_sizes, int n_in,
                              void* d_out, int out_size) {
    const float* x       = (const float*)d_in[0];
    const float* W_gat   = (const float*)d_in[1];
    const float* att_src = (const float*)d_in[2];
    const float* att_dst = (const float*)d_in[3];
    const float* b_gat   = (const float*)d_in[4];
    const float* W_gcn   = (const float*)d_in[5];
    const float* b_gcn   = (const float*)d_in[6];
    const float* W1      = (const float*)d_in[7];
    const float* b1      = (const float*)d_in[8];
    const float* W2      = (const float*)d_in[9];
    const float* b2      = (const float*)d_in[10];
    const int*   ei      = (const int*)d_in[11];

    const int N  = in_sizes[0] / D;
    const int E  = in_sizes[11] / 2;
    const int EP = E + N;
    float* out = (float*)d_out;

    float *p_xl, *p_x1, *p_xw, *p_asrc, *p_adst, *p_pmax, *p_psum, *p_h1;
    int *p_cnt, *p_rowptr, *p_cursor, *p_csrc;
    cudaGetSymbolAddress((void**)&p_xl,     g_xl);
    cudaGetSymbolAddress((void**)&p_x1,     g_x1);
    cudaGetSymbolAddress((void**)&p_xw,     g_xw);
    cudaGetSymbolAddress((void**)&p_asrc,   g_asrc);
    cudaGetSymbolAddress((void**)&p_adst,   g_adst);
    cudaGetSymbolAddress((void**)&p_pmax,   g_pmax);
    cudaGetSymbolAddress((void**)&p_psum,   g_psum);
    cudaGetSymbolAddress((void**)&p_h1,     g_h1);
    cudaGetSymbolAddress((void**)&p_cnt,    g_cnt);
    cudaGetSymbolAddress((void**)&p_rowptr, g_rowptr);
    cudaGetSymbolAddress((void**)&p_cursor, g_cursor);
    cudaGetSymbolAddress((void**)&p_csrc,   g_csrc);

    // init + CSR build
    k_init<<<cdiv(N + 2 * HD, 256), 256>>>(p_cnt, p_pmax, p_psum, N);
    k_count<<<cdiv(EP, 256), 256>>>(ei, p_cnt, E, N);
    k_scan<<<1, 1024>>>(p_cnt, p_rowptr, p_cursor, N, EP);
    k_scatter<<<cdiv(EP, 256), 256>>>(ei, p_cursor, p_csrc, E, N);
    // GEMM1 (fp32) + fused attention scores
    k_sgemm<true><<<cdiv(N, BM) * (HD / BN), 256>>>(x, W_gat, p_xl, N, HD, D,
                                                    att_src, att_dst, p_asrc, p_adst);
    // GAT softmax + aggregation
    k_gat<<<cdiv(N * 32, 256), 256>>>(p_rowptr, p_csrc, p_xl, p_asrc, p_adst,
                                      b_gat, p_x1, N);
    // GEMM2: tf32 tensor cores (double-buffered)
    k_gemm_tf32<<<cdiv(N, 128) * (HD / 128), 256>>>(p_x1, W_gcn, p_xw, N, HD, HD);
    // GCN aggregation + fused global pooling
    k_gcn_pool<<<cdiv(N * 32, 256), 256>>>(p_rowptr, p_csrc, p_cnt, p_xw, b_gcn,
                                           p_pmax, p_psum, N);
    // MLP head
    k_mlp1<<<cdiv(H1DIM, 256), 256>>>(p_pmax, p_psum, W1, b1, p_h1, N);
    k_mlp2<<<1, 256>>>(p_h1, W2, b2, out);
}